// round 16
// baseline (speedup 1.0000x reference)
#include <cuda_runtime.h>
#include <cuda_fp16.h>
#include <math.h>
#include <stdint.h>

#define NN   50000
#define NE   600000
#define IND  512
#define HID  128
#define OUTD 64
#define FAEPS 0.1f
#define NCHUNK (NE / 32)   // 18750, exact

// ---------------- scratch (static device memory; no allocs) ----------------
__device__ __align__(256) int    g_cnt[NN];
__device__ __align__(256) int    g_cur[NN];
__device__ __align__(256) int    g_off[NN + 1];
__device__ __align__(256) int4   g_e4[NE];       // {src, dst, norm_bits, 0} per CSR slot
__device__ __align__(256) float  g_dinv[NN];
__device__ __align__(256) float  g_ha[NN * HID]; // L0 out (fp32 accum)
__device__ __align__(256) float  g_hb[NN * HID]; // L1 out
__device__ __align__(256) float  g_hc[NN * HID]; // L2 out
__device__ __align__(256) __half g_h016[NN * HID];  // fp16 gather copies
__device__ __align__(256) __half g_ha16[NN * HID];
__device__ __align__(256) __half g_hb16[NN * HID];
__device__ __align__(256) float  g_alb[2][NN];
__device__ __align__(256) float  g_arb[2][NN];

__device__ __forceinline__ float* hsel(int s) {
    return s == 1 ? g_ha : (s == 2 ? g_hb : g_hc);
}
__device__ __forceinline__ __half* hsel16(int s) {
    return s == 0 ? g_h016 : (s == 1 ? g_ha16 : g_hb16);
}

__device__ __forceinline__ float my_tanh(float x) {
    float e = __expf(2.0f * x);
    return 1.0f - 2.0f / (e + 1.0f);
}

__device__ __forceinline__ uint32_t to_tf32u(float x) {
    uint32_t o;
    asm("cvt.rna.tf32.f32 %0, %1;" : "=r"(o) : "f"(x));
    return o;
}

// fp16 mma: D(4xf32) = A(4xb32) * B(2xb32) + D,  m16n8k16 row.col
__device__ __forceinline__ void mma_f16(float* c, const uint32_t* a, const uint32_t* b) {
    asm volatile(
        "mma.sync.aligned.m16n8k16.row.col.f32.f16.f16.f32 "
        "{%0,%1,%2,%3}, {%4,%5,%6,%7}, {%8,%9}, {%0,%1,%2,%3};"
        : "+f"(c[0]), "+f"(c[1]), "+f"(c[2]), "+f"(c[3])
        : "r"(a[0]), "r"(a[1]), "r"(a[2]), "r"(a[3]), "r"(b[0]), "r"(b[1]));
}

// tf32 mma (head)
__device__ __forceinline__ void mma_tf32(float* c, const uint32_t* a, const uint32_t* b) {
    asm volatile(
        "mma.sync.aligned.m16n8k8.row.col.f32.tf32.tf32.f32 "
        "{%0,%1,%2,%3}, {%4,%5,%6,%7}, {%8,%9}, {%0,%1,%2,%3};"
        : "+f"(c[0]), "+f"(c[1]), "+f"(c[2]), "+f"(c[3])
        : "r"(a[0]), "r"(a[1]), "r"(a[2]), "r"(a[3]), "r"(b[0]), "r"(b[1]));
}

__device__ __forceinline__ void red_add_v4(float* p, float4 v) {
    asm volatile("red.global.add.v4.f32 [%0], {%1,%2,%3,%4};"
                 :: "l"(p), "f"(v.x), "f"(v.y), "f"(v.z), "f"(v.w) : "memory");
}

__device__ __forceinline__ void h4_to_f4(uint2 u, float& a, float& b, float& c, float& d) {
    __half2 p0 = *(__half2*)&u.x;
    __half2 p1 = *(__half2*)&u.y;
    float2 f0 = __half22float2(p0);
    float2 f1 = __half22float2(p1);
    a = f0.x; b = f0.y; c = f1.x; d = f1.y;
}

// ---------------- graph preprocessing (4 edges/thread for MLP) -------------
__global__ void k_hist(const int* __restrict__ dst) {
    int e0 = (blockIdx.x * blockDim.x + threadIdx.x) * 4;
    if (e0 >= NE) return;
    int4 d = *(const int4*)(dst + e0);
    atomicAdd(&g_cnt[d.x], 1);
    atomicAdd(&g_cnt[d.y], 1);
    atomicAdd(&g_cnt[d.z], 1);
    atomicAdd(&g_cnt[d.w], 1);
}

__global__ void k_scan() {
    __shared__ int sums[1024];
    int tid = threadIdx.x;
    int chunk = (NN + 1023) / 1024;
    int beg = tid * chunk;
    int end = beg + chunk; if (end > NN) end = NN;
    int s = 0;
    for (int i = beg; i < end; i++) s += g_cnt[i];
    sums[tid] = s;
    __syncthreads();
    for (int off = 1; off < 1024; off <<= 1) {
        int v = 0;
        if (tid >= off) v = sums[tid - off];
        __syncthreads();
        sums[tid] += v;
        __syncthreads();
    }
    int run = (tid == 0) ? 0 : sums[tid - 1];
    for (int i = beg; i < end; i++) {
        int c = g_cnt[i];
        g_off[i] = run; run += c;
        g_dinv[i] = (c > 0) ? rsqrtf((float)c) : 0.0f;
        g_cnt[i] = 0;
        g_cur[i] = 0;
    }
    if (tid == 1023) g_off[NN] = sums[1023];
}

__global__ void k_fill(const int* __restrict__ src, const int* __restrict__ dst) {
    int e0 = (blockIdx.x * blockDim.x + threadIdx.x) * 4;
    if (e0 >= NE) return;
    int4 s4 = *(const int4*)(src + e0);
    int4 d4 = *(const int4*)(dst + e0);
    float is0 = g_dinv[s4.x], is1 = g_dinv[s4.y], is2 = g_dinv[s4.z], is3 = g_dinv[s4.w];
    float id0 = g_dinv[d4.x], id1 = g_dinv[d4.y], id2 = g_dinv[d4.z], id3 = g_dinv[d4.w];
    int k0 = g_off[d4.x] + atomicAdd(&g_cur[d4.x], 1);
    int k1 = g_off[d4.y] + atomicAdd(&g_cur[d4.y], 1);
    int k2 = g_off[d4.z] + atomicAdd(&g_cur[d4.z], 1);
    int k3 = g_off[d4.w] + atomicAdd(&g_cur[d4.w], 1);
    g_e4[k0] = make_int4(s4.x, d4.x, __float_as_int(is0 * id0), 0);
    g_e4[k1] = make_int4(s4.y, d4.y, __float_as_int(is1 * id1), 0);
    g_e4[k2] = make_int4(s4.z, d4.z, __float_as_int(is2 * id2), 0);
    g_e4[k3] = make_int4(s4.w, d4.w, __float_as_int(is3 * id3), 0);
}

// ---------------- transform 1 via fp16 mma.sync m16n8k16 -------------------
// 128x128 tile, single-buffer, two syncthreads per tile (best measured 61us).
#define SMB 20
#define GM_NT 16

__global__ __launch_bounds__(256) void k_gemm_tc(
    const float* __restrict__ X, const float* __restrict__ W,
    const float* __restrict__ B,
    const float* __restrict__ attl0, const float* __restrict__ attr0)
{
    __shared__ __align__(16) uint32_t As32[128 * SMB];
    __shared__ __align__(16) uint32_t Bs32[128 * SMB];
    __shared__ float s_pa[128], s_pb[128];

    int tid = threadIdx.x;
    int wid = tid >> 5, lane = tid & 31;
    int wr = wid >> 2, wc = wid & 3;      // warp grid 2x4: 64 rows x 32 cols
    int m0 = blockIdx.x * 128;
    int lq = lane >> 2;                    // 0..7
    int lr = lane & 3;                     // 0..3

    if (tid < 128) { s_pa[tid] = 0.f; s_pb[tid] = 0.f; }

    float acc[4][4][4];
#pragma unroll
    for (int i = 0; i < 4; i++)
#pragma unroll
        for (int j = 0; j < 4; j++)
#pragma unroll
            for (int k = 0; k < 4; k++) acc[i][j][k] = 0.f;

    float4 ra[4], rb[4];
#pragma unroll
    for (int i = 0; i < 4; i++) {
        int j = tid + 256 * i;
        int row = j >> 3, kq = j & 7;
        int m = m0 + row;
        ra[i] = (m < NN) ? *(const float4*)(X + (size_t)m * IND + kq * 4)
                         : make_float4(0.f, 0.f, 0.f, 0.f);
        rb[i] = *(const float4*)(W + (size_t)row * IND + kq * 4);
    }

    for (int t = 0; t < GM_NT; t++) {
        if (t) __syncthreads();
#pragma unroll
        for (int i = 0; i < 4; i++) {
            int j = tid + 256 * i;
            int row = j >> 3, kq = j & 7;
            __half2 a0 = __floats2half2_rn(ra[i].x, ra[i].y);
            __half2 a1 = __floats2half2_rn(ra[i].z, ra[i].w);
            __half2 b0 = __floats2half2_rn(rb[i].x, rb[i].y);
            __half2 b1 = __floats2half2_rn(rb[i].z, rb[i].w);
            uint2 au, bu;
            au.x = *(uint32_t*)&a0; au.y = *(uint32_t*)&a1;
            bu.x = *(uint32_t*)&b0; bu.y = *(uint32_t*)&b1;
            *(uint2*)(As32 + row * SMB + kq * 2) = au;
            *(uint2*)(Bs32 + row * SMB + kq * 2) = bu;
        }
        __syncthreads();
        if (t + 1 < GM_NT) {
            const float* Xb = X + (t + 1) * 32;
            const float* Wb = W + (t + 1) * 32;
#pragma unroll
            for (int i = 0; i < 4; i++) {
                int j = tid + 256 * i;
                int row = j >> 3, kq = j & 7;
                int m = m0 + row;
                ra[i] = (m < NN) ? *(const float4*)(Xb + (size_t)m * IND + kq * 4)
                                 : make_float4(0.f, 0.f, 0.f, 0.f);
                rb[i] = *(const float4*)(Wb + (size_t)row * IND + kq * 4);
            }
        }
#pragma unroll
        for (int ks = 0; ks < 2; ks++) {
            int k8 = ks * 8;
            uint32_t af[4][4], bf[4][2];
#pragma unroll
            for (int mt = 0; mt < 4; mt++) {
                int r = wr * 64 + mt * 16 + lq;
                af[mt][0] = As32[r * SMB + k8 + lr];
                af[mt][1] = As32[(r + 8) * SMB + k8 + lr];
                af[mt][2] = As32[r * SMB + k8 + lr + 4];
                af[mt][3] = As32[(r + 8) * SMB + k8 + lr + 4];
            }
#pragma unroll
            for (int nt = 0; nt < 4; nt++) {
                int n = wc * 32 + nt * 8 + lq;
                bf[nt][0] = Bs32[n * SMB + k8 + lr];
                bf[nt][1] = Bs32[n * SMB + k8 + lr + 4];
            }
#pragma unroll
            for (int mt = 0; mt < 4; mt++)
#pragma unroll
                for (int nt = 0; nt < 4; nt++)
                    mma_f16(acc[mt][nt], af[mt], bf[nt]);
        }
    }
    __syncthreads();

    // epilogue: bias+relu; h016 fp16 copy; eps -> ha,hb,hc fp32; attn dots
#pragma unroll
    for (int mt = 0; mt < 4; mt++) {
        int r0l = wr * 64 + mt * 16 + lq;
        int r1l = r0l + 8;
        int m0r = m0 + r0l, m1r = m0 + r1l;
        float dl0 = 0.f, dr0 = 0.f, dl1 = 0.f, dr1 = 0.f;
#pragma unroll
        for (int nt = 0; nt < 4; nt++) {
            int c = wc * 32 + nt * 8 + 2 * lr;
            float b0 = __ldg(B + c), b1 = __ldg(B + c + 1);
            float al0 = __ldg(attl0 + c), al1 = __ldg(attl0 + c + 1);
            float ar0 = __ldg(attr0 + c), ar1 = __ldg(attr0 + c + 1);
            float v00 = acc[mt][nt][0] + b0; v00 = v00 > 0.f ? v00 : 0.f;
            float v01 = acc[mt][nt][1] + b1; v01 = v01 > 0.f ? v01 : 0.f;
            float v10 = acc[mt][nt][2] + b0; v10 = v10 > 0.f ? v10 : 0.f;
            float v11 = acc[mt][nt][3] + b1; v11 = v11 > 0.f ? v11 : 0.f;
            dl0 = fmaf(v00, al0, fmaf(v01, al1, dl0));
            dr0 = fmaf(v00, ar0, fmaf(v01, ar1, dr0));
            dl1 = fmaf(v10, al0, fmaf(v11, al1, dl1));
            dr1 = fmaf(v10, ar0, fmaf(v11, ar1, dr1));
            if (m0r < NN) {
                size_t o = (size_t)m0r * HID + c;
                float2 ve = make_float2(FAEPS * v00, FAEPS * v01);
                *(__half2*)(g_h016 + o) = __floats2half2_rn(v00, v01);
                *(float2*)(g_ha + o) = ve;
                *(float2*)(g_hb + o) = ve;
                *(float2*)(g_hc + o) = ve;
            }
            if (m1r < NN) {
                size_t o = (size_t)m1r * HID + c;
                float2 ve = make_float2(FAEPS * v10, FAEPS * v11);
                *(__half2*)(g_h016 + o) = __floats2half2_rn(v10, v11);
                *(float2*)(g_ha + o) = ve;
                *(float2*)(g_hb + o) = ve;
                *(float2*)(g_hc + o) = ve;
            }
        }
        atomicAdd(&s_pa[r0l], dl0); atomicAdd(&s_pb[r0l], dr0);
        atomicAdd(&s_pa[r1l], dl1); atomicAdd(&s_pb[r1l], dr1);
    }
    __syncthreads();
    if (tid < 128 && m0 + tid < NN) {
        g_alb[0][m0 + tid] = s_pa[tid];
        g_arb[0][m0 + tid] = s_pb[tid];
    }
}

// ------- per-layer attn projections + fp16 copy write (warp per node) ------
__global__ __launch_bounds__(256) void k_attn(
    int h_sel, int ab_out,
    const float* __restrict__ attl, const float* __restrict__ attr)
{
    int gt = blockIdx.x * blockDim.x + threadIdx.x;
    int n = gt >> 5;
    int lane = gt & 31;
    if (n >= NN) return;
    const float4* hin4 = (const float4*)hsel(h_sel);
    float4 hv = hin4[(size_t)n * 32 + lane];
    __half2 p0 = __floats2half2_rn(hv.x, hv.y);
    __half2 p1 = __floats2half2_rn(hv.z, hv.w);
    uint2 pk;
    pk.x = *(uint32_t*)&p0;
    pk.y = *(uint32_t*)&p1;
    ((uint2*)hsel16(h_sel))[(size_t)n * 32 + lane] = pk;

    float4 la = *(const float4*)(attl + lane * 4);
    float4 ra = *(const float4*)(attr + lane * 4);
    float pa = hv.x * la.x + hv.y * la.y + hv.z * la.z + hv.w * la.w;
    float pb = hv.x * ra.x + hv.y * ra.y + hv.z * ra.z + hv.w * ra.w;
#pragma unroll
    for (int off = 16; off; off >>= 1) {
        pa += __shfl_xor_sync(0xffffffffu, pa, off);
        pb += __shfl_xor_sync(0xffffffffu, pb, off);
    }
    if (lane == 0) { g_alb[ab_out][n] = pa; g_arb[ab_out][n] = pb; }
}

// ------- chunked segmented-reduce aggregation: paired-row uint4 gather -----
// Lanes 0-15 process even-indexed edges, lanes 16-31 odd-indexed: one LDG.128
// per edge PAIR (16 lanes x 16B = full 256B row each half). Halves the gather
// instruction count at identical bytes. Each half-warp runs its own
// run-length flush (per-lane red.v4, no cross-half sync needed).
__global__ __launch_bounds__(256) void k_aggc(int hin16_sel, int hout_sel, int ab) {
    __shared__ int2  s_e[256];
    __shared__ float s_w[256];
    int tid = threadIdx.x;
    int w = tid >> 5, lane = tid & 31;
    int half = lane >> 4;       // 0: even edges, 1: odd edges
    int fl = lane & 15;         // feature chunk (8 halves = 16B)
    int chunk = blockIdx.x * 8 + w;
    if (chunk >= NCHUNK) return;
    int base = chunk * 32;
    int4 er = __ldg(&g_e4[base + lane]);   // one LDG.128: src,dst,norm
    s_e[tid] = make_int2(er.x, er.y);
    float a = my_tanh(__ldg(&g_alb[ab][er.x]) + __ldg(&g_arb[ab][er.y]));
    s_w[tid] = a * __int_as_float(er.z);
    __syncwarp();
    const uint4* __restrict__ h4p = (const uint4*)hsel16(hin16_sel);
    float* __restrict__ hout = hsel(hout_sel);
    // per-lane accumulator: 8 floats (feature chunk fl of this half's run)
    float accv[8];
#pragma unroll
    for (int i = 0; i < 8; i++) accv[i] = 0.f;
    int sb = w * 32;

#pragma unroll
    for (int g = 0; g < 4; g++) {
        // batch-load 4 pairs: pair i = g*4+p covers edges 2i (half0), 2i+1 (half1)
        uint4 v[4];
        int e_idx[4];
#pragma unroll
        for (int p = 0; p < 4; p++) {
            int i = g * 4 + p;
            int e = 2 * i + half;
            e_idx[p] = e;
            int srow = s_e[sb + e].x;
            v[p] = __ldg(h4p + (size_t)srow * 16 + fl);
        }
#pragma unroll
        for (int p = 0; p < 4; p++) {
            int e = e_idx[p];
            float wv = s_w[sb + e];
            __half2 q0 = *(__half2*)&v[p].x;
            __half2 q1 = *(__half2*)&v[p].y;
            __half2 q2 = *(__half2*)&v[p].z;
            __half2 q3 = *(__half2*)&v[p].w;
            float2 f0 = __half22float2(q0);
            float2 f1 = __half22float2(q1);
            float2 f2 = __half22float2(q2);
            float2 f3 = __half22float2(q3);
            accv[0] = fmaf(wv, f0.x, accv[0]);
            accv[1] = fmaf(wv, f0.y, accv[1]);
            accv[2] = fmaf(wv, f1.x, accv[2]);
            accv[3] = fmaf(wv, f1.y, accv[3]);
            accv[4] = fmaf(wv, f2.x, accv[4]);
            accv[5] = fmaf(wv, f2.y, accv[5]);
            accv[6] = fmaf(wv, f3.x, accv[6]);
            accv[7] = fmaf(wv, f3.y, accv[7]);
            // flush when this half's NEXT edge has a different dst
            int mydst = s_e[sb + e].y;
            int dn;
            if (g == 3 && p == 3) dn = -1;
            else dn = s_e[sb + e + 2].y;
            if (mydst != dn) {
                float* pdst = hout + (size_t)mydst * HID + fl * 8;
                red_add_v4(pdst, make_float4(accv[0], accv[1], accv[2], accv[3]));
                red_add_v4(pdst + 4, make_float4(accv[4], accv[5], accv[6], accv[7]));
#pragma unroll
                for (int i = 0; i < 8; i++) accv[i] = 0.f;
            }
        }
    }
}

// ---------------- head via tf32 mma + fused log_softmax -------------------
#define SMS 36
__global__ __launch_bounds__(256) void k_head_mma(
    int hin_sel, const float* __restrict__ W2,
    const float* __restrict__ B2, float* __restrict__ out, int write_emb)
{
    __shared__ __align__(16) union { float A[128 * SMS]; float E[128 * 68]; } uA;
    __shared__ __align__(16) float Bs[64 * SMS];
    int tid = threadIdx.x;
    int wid = tid >> 5, lane = tid & 31;
    int wr = wid >> 1, wc = wid & 1;
    int m0 = blockIdx.x * 128;
    int lq = lane >> 2, lr = lane & 3;
    const float* h = hsel(hin_sel);

    float acc[2][4][4];
#pragma unroll
    for (int i = 0; i < 2; i++)
#pragma unroll
        for (int j = 0; j < 4; j++)
#pragma unroll
            for (int k = 0; k < 4; k++) acc[i][j][k] = 0.f;

    float4 ra[4], rb[2];
#pragma unroll
    for (int i = 0; i < 4; i++) {
        int j = tid + 256 * i;
        int row = j >> 3, kq = j & 7;
        int m = m0 + row;
        ra[i] = (m < NN) ? *(const float4*)(h + (size_t)m * HID + kq * 4)
                         : make_float4(0.f, 0.f, 0.f, 0.f);
    }
#pragma unroll
    for (int i = 0; i < 2; i++) {
        int j = tid + 256 * i;
        if (j < 512) {
            int row = j >> 3, kq = j & 7;
            rb[i] = *(const float4*)(W2 + (size_t)row * HID + kq * 4);
        }
    }

    for (int t = 0; t < 4; t++) {
        if (t) __syncthreads();
#pragma unroll
        for (int i = 0; i < 4; i++) {
            int j = tid + 256 * i;
            int row = j >> 3, kq = j & 7;
            float* ap = uA.A + row * SMS + kq * 4;
            ap[0] = __uint_as_float(to_tf32u(ra[i].x));
            ap[1] = __uint_as_float(to_tf32u(ra[i].y));
            ap[2] = __uint_as_float(to_tf32u(ra[i].z));
            ap[3] = __uint_as_float(to_tf32u(ra[i].w));
        }
#pragma unroll
        for (int i = 0; i < 2; i++) {
            int j = tid + 256 * i;
            if (j < 512) {
                int row = j >> 3, kq = j & 7;
                float* bp = Bs + row * SMS + kq * 4;
                bp[0] = __uint_as_float(to_tf32u(rb[i].x));
                bp[1] = __uint_as_float(to_tf32u(rb[i].y));
                bp[2] = __uint_as_float(to_tf32u(rb[i].z));
                bp[3] = __uint_as_float(to_tf32u(rb[i].w));
            }
        }
        __syncthreads();
        if (t + 1 < 4) {
            const float* Hb = h + (t + 1) * 32;
            const float* Wb = W2 + (t + 1) * 32;
#pragma unroll
            for (int i = 0; i < 4; i++) {
                int j = tid + 256 * i;
                int row = j >> 3, kq = j & 7;
                int m = m0 + row;
                ra[i] = (m < NN) ? *(const float4*)(Hb + (size_t)m * HID + kq * 4)
                                 : make_float4(0.f, 0.f, 0.f, 0.f);
            }
#pragma unroll
            for (int i = 0; i < 2; i++) {
                int j = tid + 256 * i;
                if (j < 512) {
                    int row = j >> 3, kq = j & 7;
                    rb[i] = *(const float4*)(Wb + (size_t)row * HID + kq * 4);
                }
            }
        }
#pragma unroll
        for (int kk = 0; kk < 32; kk += 8) {
            uint32_t af[2][4], bf[4][2];
#pragma unroll
            for (int mt = 0; mt < 2; mt++) {
                const float* ap = uA.A + (wr * 32 + mt * 16 + lq) * SMS + kk + lr;
                af[mt][0] = __float_as_uint(ap[0]);
                af[mt][1] = __float_as_uint(ap[8 * SMS]);
                af[mt][2] = __float_as_uint(ap[4]);
                af[mt][3] = __float_as_uint(ap[8 * SMS + 4]);
            }
#pragma unroll
            for (int nt = 0; nt < 4; nt++) {
                const float* bp = Bs + (wc * 32 + nt * 8 + lq) * SMS + kk + lr;
                bf[nt][0] = __float_as_uint(bp[0]);
                bf[nt][1] = __float_as_uint(bp[4]);
            }
#pragma unroll
            for (int mt = 0; mt < 2; mt++)
#pragma unroll
                for (int nt = 0; nt < 4; nt++)
                    mma_tf32(acc[mt][nt], af[mt], bf[nt]);
        }
    }
    __syncthreads();

#pragma unroll
    for (int mt = 0; mt < 2; mt++) {
        int r0 = wr * 32 + mt * 16 + lq;
        int r1 = r0 + 8;
#pragma unroll
        for (int nt = 0; nt < 4; nt++) {
            int c = wc * 32 + nt * 8 + 2 * lr;
            float b0 = __ldg(B2 + c), b1 = __ldg(B2 + c + 1);
            uA.E[r0 * 68 + c]     = acc[mt][nt][0] + b0;
            uA.E[r0 * 68 + c + 1] = acc[mt][nt][1] + b1;
            uA.E[r1 * 68 + c]     = acc[mt][nt][2] + b0;
            uA.E[r1 * 68 + c + 1] = acc[mt][nt][3] + b1;
        }
    }
    __syncthreads();

    int r = tid >> 1, hf = tid & 1;
    int n = m0 + r;
    const float* er = &uA.E[r * 68 + hf * 32];
    float4 q[8];
#pragma unroll
    for (int i = 0; i < 8; i++) q[i] = ((const float4*)er)[i];
    float m = q[0].x;
#pragma unroll
    for (int i = 0; i < 8; i++)
        m = fmaxf(m, fmaxf(fmaxf(q[i].x, q[i].y), fmaxf(q[i].z, q[i].w)));
    m = fmaxf(m, __shfl_xor_sync(0xffffffffu, m, 1));
    float se = 0.f;
#pragma unroll
    for (int i = 0; i < 8; i++)
        se += expf(q[i].x - m) + expf(q[i].y - m) + expf(q[i].z - m) + expf(q[i].w - m);
    se += __shfl_xor_sync(0xffffffffu, se, 1);
    float lse = m + logf(se);

    if (n < NN) {
        size_t base = (size_t)n * OUTD + hf * 32;
#pragma unroll
        for (int i = 0; i < 8; i++)
            *(float4*)(out + base + i * 4) =
                make_float4(q[i].x - lse, q[i].y - lse, q[i].z - lse, q[i].w - lse);
        if (write_emb) {
            float* emb = out + (size_t)NN * OUTD;
#pragma unroll
            for (int i = 0; i < 8; i++)
                *(float4*)(emb + base + i * 4) = q[i];
        }
    }
}

// ---------------- launch ----------------
extern "C" void kernel_launch(void* const* d_in, const int* in_sizes, int n_in,
                              void* d_out, int out_size) {
    const float* x    = (const float*)d_in[0];
    const int*   ei   = (const int*)d_in[1];
    const int*   src  = ei;
    const int*   dst  = ei + NE;
    const float* t1w  = (const float*)d_in[2];
    const float* t1b  = (const float*)d_in[3];
    const float* t2w  = (const float*)d_in[4];
    const float* t2b  = (const float*)d_in[5];
    const float* attl = (const float*)d_in[6];
    const float* attr = (const float*)d_in[7];
    float* out = (float*)d_out;
    int write_emb = (out_size >= 2 * NN * OUTD) ? 1 : 0;

    const int TB = 256;
    int gE4 = (NE / 4 + TB - 1) / TB;
    int gW = (NN * 32 + TB - 1) / TB;
    int gC = (NCHUNK + 7) / 8;

    k_hist<<<gE4, TB>>>(dst);
    k_scan<<<1, 1024>>>();
    k_fill<<<gE4, TB>>>(src, dst);
    k_gemm_tc<<<(NN + 127) / 128, 256>>>(x, t1w, t1b, attl, attr);  // 4th: profiled

    k_aggc<<<gC, TB>>>(0, 1, 0);
    k_attn<<<gW, TB>>>(1, 1, attl + 1 * HID, attr + 1 * HID);
    k_aggc<<<gC, TB>>>(1, 2, 1);
    k_attn<<<gW, TB>>>(2, 0, attl + 2 * HID, attr + 2 * HID);
    k_aggc<<<gC, TB>>>(2, 3, 0);

    k_head_mma<<<(NN + 127) / 128, 256>>>(3, t2w, t2b, out, write_emb);
}

// round 17
// speedup vs baseline: 1.1976x; 1.1976x over previous
#include <cuda_runtime.h>
#include <cuda_fp16.h>
#include <math.h>
#include <stdint.h>

#define NN   50000
#define NE   600000
#define IND  512
#define HID  128
#define OUTD 64
#define FAEPS 0.1f
#define NCHUNK (NE / 32)   // 18750, exact

// ---------------- scratch (static device memory; no allocs) ----------------
__device__ __align__(256) int    g_cnt[NN];
__device__ __align__(256) int    g_cur[NN];
__device__ __align__(256) int    g_off[NN + 1];
__device__ __align__(256) int4   g_e4[NE];       // {src, dst, norm_bits, 0} per CSR slot
__device__ __align__(256) float  g_dinv[NN];
__device__ __align__(256) float  g_ha[NN * HID]; // L0 out (fp32 accum)
__device__ __align__(256) float  g_hb[NN * HID]; // L1 out
__device__ __align__(256) float  g_hc[NN * HID]; // L2 out
__device__ __align__(256) __half g_h016[NN * HID];  // fp16 gather copies
__device__ __align__(256) __half g_ha16[NN * HID];
__device__ __align__(256) __half g_hb16[NN * HID];
__device__ __align__(256) float  g_alb[2][NN];
__device__ __align__(256) float  g_arb[2][NN];

__device__ __forceinline__ float* hsel(int s) {
    return s == 1 ? g_ha : (s == 2 ? g_hb : g_hc);
}
__device__ __forceinline__ __half* hsel16(int s) {
    return s == 0 ? g_h016 : (s == 1 ? g_ha16 : g_hb16);
}

__device__ __forceinline__ float my_tanh(float x) {
    float e = expf(2.0f * x);
    return 1.0f - 2.0f / (e + 1.0f);
}

__device__ __forceinline__ uint32_t to_tf32u(float x) {
    uint32_t o;
    asm("cvt.rna.tf32.f32 %0, %1;" : "=r"(o) : "f"(x));
    return o;
}

// fp16 mma: D(4xf32) = A(4xb32) * B(2xb32) + D,  m16n8k16 row.col
__device__ __forceinline__ void mma_f16(float* c, const uint32_t* a, const uint32_t* b) {
    asm volatile(
        "mma.sync.aligned.m16n8k16.row.col.f32.f16.f16.f32 "
        "{%0,%1,%2,%3}, {%4,%5,%6,%7}, {%8,%9}, {%0,%1,%2,%3};"
        : "+f"(c[0]), "+f"(c[1]), "+f"(c[2]), "+f"(c[3])
        : "r"(a[0]), "r"(a[1]), "r"(a[2]), "r"(a[3]), "r"(b[0]), "r"(b[1]));
}

// tf32 mma (head)
__device__ __forceinline__ void mma_tf32(float* c, const uint32_t* a, const uint32_t* b) {
    asm volatile(
        "mma.sync.aligned.m16n8k8.row.col.f32.tf32.tf32.f32 "
        "{%0,%1,%2,%3}, {%4,%5,%6,%7}, {%8,%9}, {%0,%1,%2,%3};"
        : "+f"(c[0]), "+f"(c[1]), "+f"(c[2]), "+f"(c[3])
        : "r"(a[0]), "r"(a[1]), "r"(a[2]), "r"(a[3]), "r"(b[0]), "r"(b[1]));
}

__device__ __forceinline__ void red_add_v4(float* p, float4 v) {
    asm volatile("red.global.add.v4.f32 [%0], {%1,%2,%3,%4};"
                 :: "l"(p), "f"(v.x), "f"(v.y), "f"(v.z), "f"(v.w) : "memory");
}

__device__ __forceinline__ void h4_to_f4(uint2 u, float& a, float& b, float& c, float& d) {
    __half2 p0 = *(__half2*)&u.x;
    __half2 p1 = *(__half2*)&u.y;
    float2 f0 = __half22float2(p0);
    float2 f1 = __half22float2(p1);
    a = f0.x; b = f0.y; c = f1.x; d = f1.y;
}

// ---------------- graph preprocessing (4 edges/thread for MLP) -------------
__global__ void k_hist(const int* __restrict__ dst) {
    int e0 = (blockIdx.x * blockDim.x + threadIdx.x) * 4;
    if (e0 >= NE) return;
    int4 d = *(const int4*)(dst + e0);
    atomicAdd(&g_cnt[d.x], 1);
    atomicAdd(&g_cnt[d.y], 1);
    atomicAdd(&g_cnt[d.z], 1);
    atomicAdd(&g_cnt[d.w], 1);
}

__global__ void k_scan() {
    __shared__ int sums[1024];
    int tid = threadIdx.x;
    int chunk = (NN + 1023) / 1024;
    int beg = tid * chunk;
    int end = beg + chunk; if (end > NN) end = NN;
    int s = 0;
    for (int i = beg; i < end; i++) s += g_cnt[i];
    sums[tid] = s;
    __syncthreads();
    for (int off = 1; off < 1024; off <<= 1) {
        int v = 0;
        if (tid >= off) v = sums[tid - off];
        __syncthreads();
        sums[tid] += v;
        __syncthreads();
    }
    int run = (tid == 0) ? 0 : sums[tid - 1];
    for (int i = beg; i < end; i++) {
        int c = g_cnt[i];
        g_off[i] = run; run += c;
        g_dinv[i] = (c > 0) ? rsqrtf((float)c) : 0.0f;
        g_cnt[i] = 0;
        g_cur[i] = 0;
    }
    if (tid == 1023) g_off[NN] = sums[1023];
}

__global__ void k_fill(const int* __restrict__ src, const int* __restrict__ dst) {
    int e0 = (blockIdx.x * blockDim.x + threadIdx.x) * 4;
    if (e0 >= NE) return;
    int4 s4 = *(const int4*)(src + e0);
    int4 d4 = *(const int4*)(dst + e0);
    float is0 = g_dinv[s4.x], is1 = g_dinv[s4.y], is2 = g_dinv[s4.z], is3 = g_dinv[s4.w];
    float id0 = g_dinv[d4.x], id1 = g_dinv[d4.y], id2 = g_dinv[d4.z], id3 = g_dinv[d4.w];
    int k0 = g_off[d4.x] + atomicAdd(&g_cur[d4.x], 1);
    int k1 = g_off[d4.y] + atomicAdd(&g_cur[d4.y], 1);
    int k2 = g_off[d4.z] + atomicAdd(&g_cur[d4.z], 1);
    int k3 = g_off[d4.w] + atomicAdd(&g_cur[d4.w], 1);
    g_e4[k0] = make_int4(s4.x, d4.x, __float_as_int(is0 * id0), 0);
    g_e4[k1] = make_int4(s4.y, d4.y, __float_as_int(is1 * id1), 0);
    g_e4[k2] = make_int4(s4.z, d4.z, __float_as_int(is2 * id2), 0);
    g_e4[k3] = make_int4(s4.w, d4.w, __float_as_int(is3 * id3), 0);
}

// ---------------- transform 1 via fp16 mma.sync m16n8k16 -------------------
// 128x128 tile, single-buffer, two syncthreads per tile (best measured 61us).
#define SMB 20
#define GM_NT 16

__global__ __launch_bounds__(256) void k_gemm_tc(
    const float* __restrict__ X, const float* __restrict__ W,
    const float* __restrict__ B,
    const float* __restrict__ attl0, const float* __restrict__ attr0)
{
    __shared__ __align__(16) uint32_t As32[128 * SMB];
    __shared__ __align__(16) uint32_t Bs32[128 * SMB];
    __shared__ float s_pa[128], s_pb[128];

    int tid = threadIdx.x;
    int wid = tid >> 5, lane = tid & 31;
    int wr = wid >> 2, wc = wid & 3;      // warp grid 2x4: 64 rows x 32 cols
    int m0 = blockIdx.x * 128;
    int lq = lane >> 2;                    // 0..7
    int lr = lane & 3;                     // 0..3

    if (tid < 128) { s_pa[tid] = 0.f; s_pb[tid] = 0.f; }

    float acc[4][4][4];
#pragma unroll
    for (int i = 0; i < 4; i++)
#pragma unroll
        for (int j = 0; j < 4; j++)
#pragma unroll
            for (int k = 0; k < 4; k++) acc[i][j][k] = 0.f;

    float4 ra[4], rb[4];
#pragma unroll
    for (int i = 0; i < 4; i++) {
        int j = tid + 256 * i;
        int row = j >> 3, kq = j & 7;
        int m = m0 + row;
        ra[i] = (m < NN) ? *(const float4*)(X + (size_t)m * IND + kq * 4)
                         : make_float4(0.f, 0.f, 0.f, 0.f);
        rb[i] = *(const float4*)(W + (size_t)row * IND + kq * 4);
    }

    for (int t = 0; t < GM_NT; t++) {
        if (t) __syncthreads();
#pragma unroll
        for (int i = 0; i < 4; i++) {
            int j = tid + 256 * i;
            int row = j >> 3, kq = j & 7;
            __half2 a0 = __floats2half2_rn(ra[i].x, ra[i].y);
            __half2 a1 = __floats2half2_rn(ra[i].z, ra[i].w);
            __half2 b0 = __floats2half2_rn(rb[i].x, rb[i].y);
            __half2 b1 = __floats2half2_rn(rb[i].z, rb[i].w);
            uint2 au, bu;
            au.x = *(uint32_t*)&a0; au.y = *(uint32_t*)&a1;
            bu.x = *(uint32_t*)&b0; bu.y = *(uint32_t*)&b1;
            *(uint2*)(As32 + row * SMB + kq * 2) = au;
            *(uint2*)(Bs32 + row * SMB + kq * 2) = bu;
        }
        __syncthreads();
        if (t + 1 < GM_NT) {
            const float* Xb = X + (t + 1) * 32;
            const float* Wb = W + (t + 1) * 32;
#pragma unroll
            for (int i = 0; i < 4; i++) {
                int j = tid + 256 * i;
                int row = j >> 3, kq = j & 7;
                int m = m0 + row;
                ra[i] = (m < NN) ? *(const float4*)(Xb + (size_t)m * IND + kq * 4)
                                 : make_float4(0.f, 0.f, 0.f, 0.f);
                rb[i] = *(const float4*)(Wb + (size_t)row * IND + kq * 4);
            }
        }
#pragma unroll
        for (int ks = 0; ks < 2; ks++) {
            int k8 = ks * 8;
            uint32_t af[4][4], bf[4][2];
#pragma unroll
            for (int mt = 0; mt < 4; mt++) {
                int r = wr * 64 + mt * 16 + lq;
                af[mt][0] = As32[r * SMB + k8 + lr];
                af[mt][1] = As32[(r + 8) * SMB + k8 + lr];
                af[mt][2] = As32[r * SMB + k8 + lr + 4];
                af[mt][3] = As32[(r + 8) * SMB + k8 + lr + 4];
            }
#pragma unroll
            for (int nt = 0; nt < 4; nt++) {
                int n = wc * 32 + nt * 8 + lq;
                bf[nt][0] = Bs32[n * SMB + k8 + lr];
                bf[nt][1] = Bs32[n * SMB + k8 + lr + 4];
            }
#pragma unroll
            for (int mt = 0; mt < 4; mt++)
#pragma unroll
                for (int nt = 0; nt < 4; nt++)
                    mma_f16(acc[mt][nt], af[mt], bf[nt]);
        }
    }
    __syncthreads();

    // epilogue: bias+relu; h016 fp16 copy; eps -> ha,hb,hc fp32; attn dots
#pragma unroll
    for (int mt = 0; mt < 4; mt++) {
        int r0l = wr * 64 + mt * 16 + lq;
        int r1l = r0l + 8;
        int m0r = m0 + r0l, m1r = m0 + r1l;
        float dl0 = 0.f, dr0 = 0.f, dl1 = 0.f, dr1 = 0.f;
#pragma unroll
        for (int nt = 0; nt < 4; nt++) {
            int c = wc * 32 + nt * 8 + 2 * lr;
            float b0 = __ldg(B + c), b1 = __ldg(B + c + 1);
            float al0 = __ldg(attl0 + c), al1 = __ldg(attl0 + c + 1);
            float ar0 = __ldg(attr0 + c), ar1 = __ldg(attr0 + c + 1);
            float v00 = acc[mt][nt][0] + b0; v00 = v00 > 0.f ? v00 : 0.f;
            float v01 = acc[mt][nt][1] + b1; v01 = v01 > 0.f ? v01 : 0.f;
            float v10 = acc[mt][nt][2] + b0; v10 = v10 > 0.f ? v10 : 0.f;
            float v11 = acc[mt][nt][3] + b1; v11 = v11 > 0.f ? v11 : 0.f;
            dl0 = fmaf(v00, al0, fmaf(v01, al1, dl0));
            dr0 = fmaf(v00, ar0, fmaf(v01, ar1, dr0));
            dl1 = fmaf(v10, al0, fmaf(v11, al1, dl1));
            dr1 = fmaf(v10, ar0, fmaf(v11, ar1, dr1));
            if (m0r < NN) {
                size_t o = (size_t)m0r * HID + c;
                float2 ve = make_float2(FAEPS * v00, FAEPS * v01);
                *(__half2*)(g_h016 + o) = __floats2half2_rn(v00, v01);
                *(float2*)(g_ha + o) = ve;
                *(float2*)(g_hb + o) = ve;
                *(float2*)(g_hc + o) = ve;
            }
            if (m1r < NN) {
                size_t o = (size_t)m1r * HID + c;
                float2 ve = make_float2(FAEPS * v10, FAEPS * v11);
                *(__half2*)(g_h016 + o) = __floats2half2_rn(v10, v11);
                *(float2*)(g_ha + o) = ve;
                *(float2*)(g_hb + o) = ve;
                *(float2*)(g_hc + o) = ve;
            }
        }
        atomicAdd(&s_pa[r0l], dl0); atomicAdd(&s_pb[r0l], dr0);
        atomicAdd(&s_pa[r1l], dl1); atomicAdd(&s_pb[r1l], dr1);
    }
    __syncthreads();
    if (tid < 128 && m0 + tid < NN) {
        g_alb[0][m0 + tid] = s_pa[tid];
        g_arb[0][m0 + tid] = s_pb[tid];
    }
}

// ------- per-layer attn projections + fp16 copy write (warp per node) ------
__global__ __launch_bounds__(256) void k_attn(
    int h_sel, int ab_out,
    const float* __restrict__ attl, const float* __restrict__ attr)
{
    int gt = blockIdx.x * blockDim.x + threadIdx.x;
    int n = gt >> 5;
    int lane = gt & 31;
    if (n >= NN) return;
    const float4* hin4 = (const float4*)hsel(h_sel);
    float4 hv = hin4[(size_t)n * 32 + lane];
    __half2 p0 = __floats2half2_rn(hv.x, hv.y);
    __half2 p1 = __floats2half2_rn(hv.z, hv.w);
    uint2 pk;
    pk.x = *(uint32_t*)&p0;
    pk.y = *(uint32_t*)&p1;
    ((uint2*)hsel16(h_sel))[(size_t)n * 32 + lane] = pk;

    float4 la = *(const float4*)(attl + lane * 4);
    float4 ra = *(const float4*)(attr + lane * 4);
    float pa = hv.x * la.x + hv.y * la.y + hv.z * la.z + hv.w * la.w;
    float pb = hv.x * ra.x + hv.y * ra.y + hv.z * ra.z + hv.w * ra.w;
#pragma unroll
    for (int off = 16; off; off >>= 1) {
        pa += __shfl_xor_sync(0xffffffffu, pa, off);
        pb += __shfl_xor_sync(0xffffffffu, pb, off);
    }
    if (lane == 0) { g_alb[ab_out][n] = pa; g_arb[ab_out][n] = pb; }
}

// ------- chunked segmented-reduce aggregation: 32 edges/warp, int4 recs ----
__global__ __launch_bounds__(256) void k_aggc(int hin16_sel, int hout_sel, int ab) {
    __shared__ int2  s_e[256];
    __shared__ float s_w[256];
    int tid = threadIdx.x;
    int w = tid >> 5, lane = tid & 31;
    int chunk = blockIdx.x * 8 + w;
    if (chunk >= NCHUNK) return;
    int base = chunk * 32;
    int4 er = __ldg(&g_e4[base + lane]);   // one LDG.128: src,dst,norm
    s_e[tid] = make_int2(er.x, er.y);
    float a = my_tanh(__ldg(&g_alb[ab][er.x]) + __ldg(&g_arb[ab][er.y]));
    s_w[tid] = a * __int_as_float(er.z);
    __syncwarp();
    const uint2* __restrict__ h2 = (const uint2*)hsel16(hin16_sel);
    float* __restrict__ hout = hsel(hout_sel);
    float4 acc = make_float4(0.f, 0.f, 0.f, 0.f);
    int sb = w * 32;
#pragma unroll
    for (int g = 0; g < 4; g++) {
        int2 ed[8]; float wv[8];
#pragma unroll
        for (int jj = 0; jj < 8; jj++) {
            ed[jj] = s_e[sb + g * 8 + jj];
            wv[jj] = s_w[sb + g * 8 + jj];
        }
        uint2 v[8];
#pragma unroll
        for (int jj = 0; jj < 8; jj++)
            v[jj] = __ldg(h2 + (size_t)ed[jj].x * 32 + lane);
#pragma unroll
        for (int jj = 0; jj < 8; jj++) {
            float fx, fy, fz, fw;
            h4_to_f4(v[jj], fx, fy, fz, fw);
            acc.x = fmaf(wv[jj], fx, acc.x);
            acc.y = fmaf(wv[jj], fy, acc.y);
            acc.z = fmaf(wv[jj], fz, acc.z);
            acc.w = fmaf(wv[jj], fw, acc.w);
            int dn;
            if (g == 3 && jj == 7) dn = -1;
            else if (jj < 7) dn = ed[jj + 1].y;
            else dn = s_e[sb + g * 8 + 8].y;
            if (ed[jj].y != dn) {
                red_add_v4(hout + (size_t)ed[jj].y * HID + lane * 4, acc);
                acc = make_float4(0.f, 0.f, 0.f, 0.f);
            }
        }
    }
}

// ---------------- head via tf32 mma + fused log_softmax -------------------
#define SMS 36
__global__ __launch_bounds__(256) void k_head_mma(
    int hin_sel, const float* __restrict__ W2,
    const float* __restrict__ B2, float* __restrict__ out, int write_emb)
{
    __shared__ __align__(16) union { float A[128 * SMS]; float E[128 * 68]; } uA;
    __shared__ __align__(16) float Bs[64 * SMS];
    int tid = threadIdx.x;
    int wid = tid >> 5, lane = tid & 31;
    int wr = wid >> 1, wc = wid & 1;
    int m0 = blockIdx.x * 128;
    int lq = lane >> 2, lr = lane & 3;
    const float* h = hsel(hin_sel);

    float acc[2][4][4];
#pragma unroll
    for (int i = 0; i < 2; i++)
#pragma unroll
        for (int j = 0; j < 4; j++)
#pragma unroll
            for (int k = 0; k < 4; k++) acc[i][j][k] = 0.f;

    float4 ra[4], rb[2];
#pragma unroll
    for (int i = 0; i < 4; i++) {
        int j = tid + 256 * i;
        int row = j >> 3, kq = j & 7;
        int m = m0 + row;
        ra[i] = (m < NN) ? *(const float4*)(h + (size_t)m * HID + kq * 4)
                         : make_float4(0.f, 0.f, 0.f, 0.f);
    }
#pragma unroll
    for (int i = 0; i < 2; i++) {
        int j = tid + 256 * i;
        if (j < 512) {
            int row = j >> 3, kq = j & 7;
            rb[i] = *(const float4*)(W2 + (size_t)row * HID + kq * 4);
        }
    }

    for (int t = 0; t < 4; t++) {
        if (t) __syncthreads();
#pragma unroll
        for (int i = 0; i < 4; i++) {
            int j = tid + 256 * i;
            int row = j >> 3, kq = j & 7;
            float* ap = uA.A + row * SMS + kq * 4;
            ap[0] = __uint_as_float(to_tf32u(ra[i].x));
            ap[1] = __uint_as_float(to_tf32u(ra[i].y));
            ap[2] = __uint_as_float(to_tf32u(ra[i].z));
            ap[3] = __uint_as_float(to_tf32u(ra[i].w));
        }
#pragma unroll
        for (int i = 0; i < 2; i++) {
            int j = tid + 256 * i;
            if (j < 512) {
                int row = j >> 3, kq = j & 7;
                float* bp = Bs + row * SMS + kq * 4;
                bp[0] = __uint_as_float(to_tf32u(rb[i].x));
                bp[1] = __uint_as_float(to_tf32u(rb[i].y));
                bp[2] = __uint_as_float(to_tf32u(rb[i].z));
                bp[3] = __uint_as_float(to_tf32u(rb[i].w));
            }
        }
        __syncthreads();
        if (t + 1 < 4) {
            const float* Hb = h + (t + 1) * 32;
            const float* Wb = W2 + (t + 1) * 32;
#pragma unroll
            for (int i = 0; i < 4; i++) {
                int j = tid + 256 * i;
                int row = j >> 3, kq = j & 7;
                int m = m0 + row;
                ra[i] = (m < NN) ? *(const float4*)(Hb + (size_t)m * HID + kq * 4)
                                 : make_float4(0.f, 0.f, 0.f, 0.f);
            }
#pragma unroll
            for (int i = 0; i < 2; i++) {
                int j = tid + 256 * i;
                if (j < 512) {
                    int row = j >> 3, kq = j & 7;
                    rb[i] = *(const float4*)(Wb + (size_t)row * HID + kq * 4);
                }
            }
        }
#pragma unroll
        for (int kk = 0; kk < 32; kk += 8) {
            uint32_t af[2][4], bf[4][2];
#pragma unroll
            for (int mt = 0; mt < 2; mt++) {
                const float* ap = uA.A + (wr * 32 + mt * 16 + lq) * SMS + kk + lr;
                af[mt][0] = __float_as_uint(ap[0]);
                af[mt][1] = __float_as_uint(ap[8 * SMS]);
                af[mt][2] = __float_as_uint(ap[4]);
                af[mt][3] = __float_as_uint(ap[8 * SMS + 4]);
            }
#pragma unroll
            for (int nt = 0; nt < 4; nt++) {
                const float* bp = Bs + (wc * 32 + nt * 8 + lq) * SMS + kk + lr;
                bf[nt][0] = __float_as_uint(bp[0]);
                bf[nt][1] = __float_as_uint(bp[4]);
            }
#pragma unroll
            for (int mt = 0; mt < 2; mt++)
#pragma unroll
                for (int nt = 0; nt < 4; nt++)
                    mma_tf32(acc[mt][nt], af[mt], bf[nt]);
        }
    }
    __syncthreads();

#pragma unroll
    for (int mt = 0; mt < 2; mt++) {
        int r0 = wr * 32 + mt * 16 + lq;
        int r1 = r0 + 8;
#pragma unroll
        for (int nt = 0; nt < 4; nt++) {
            int c = wc * 32 + nt * 8 + 2 * lr;
            float b0 = __ldg(B2 + c), b1 = __ldg(B2 + c + 1);
            uA.E[r0 * 68 + c]     = acc[mt][nt][0] + b0;
            uA.E[r0 * 68 + c + 1] = acc[mt][nt][1] + b1;
            uA.E[r1 * 68 + c]     = acc[mt][nt][2] + b0;
            uA.E[r1 * 68 + c + 1] = acc[mt][nt][3] + b1;
        }
    }
    __syncthreads();

    int r = tid >> 1, hf = tid & 1;
    int n = m0 + r;
    const float* er = &uA.E[r * 68 + hf * 32];
    float4 q[8];
#pragma unroll
    for (int i = 0; i < 8; i++) q[i] = ((const float4*)er)[i];
    float m = q[0].x;
#pragma unroll
    for (int i = 0; i < 8; i++)
        m = fmaxf(m, fmaxf(fmaxf(q[i].x, q[i].y), fmaxf(q[i].z, q[i].w)));
    m = fmaxf(m, __shfl_xor_sync(0xffffffffu, m, 1));
    float se = 0.f;
#pragma unroll
    for (int i = 0; i < 8; i++)
        se += expf(q[i].x - m) + expf(q[i].y - m) + expf(q[i].z - m) + expf(q[i].w - m);
    se += __shfl_xor_sync(0xffffffffu, se, 1);
    float lse = m + logf(se);

    if (n < NN) {
        size_t base = (size_t)n * OUTD + hf * 32;
#pragma unroll
        for (int i = 0; i < 8; i++)
            *(float4*)(out + base + i * 4) =
                make_float4(q[i].x - lse, q[i].y - lse, q[i].z - lse, q[i].w - lse);
        if (write_emb) {
            float* emb = out + (size_t)NN * OUTD;
#pragma unroll
            for (int i = 0; i < 8; i++)
                *(float4*)(emb + base + i * 4) = q[i];
        }
    }
}

// ---------------- launch ----------------
extern "C" void kernel_launch(void* const* d_in, const int* in_sizes, int n_in,
                              void* d_out, int out_size) {
    const float* x    = (const float*)d_in[0];
    const int*   ei   = (const int*)d_in[1];
    const int*   src  = ei;
    const int*   dst  = ei + NE;
    const float* t1w  = (const float*)d_in[2];
    const float* t1b  = (const float*)d_in[3];
    const float* t2w  = (const float*)d_in[4];
    const float* t2b  = (const float*)d_in[5];
    const float* attl = (const float*)d_in[6];
    const float* attr = (const float*)d_in[7];
    float* out = (float*)d_out;
    int write_emb = (out_size >= 2 * NN * OUTD) ? 1 : 0;

    // lazily created side stream + events (host-side resources only; the
    // captured graph topology is identical on every call)
    static cudaStream_t s2 = nullptr;
    static cudaEvent_t ev_fork = nullptr, ev_join = nullptr;
    if (s2 == nullptr) {
        cudaStreamCreateWithFlags(&s2, cudaStreamNonBlocking);
        cudaEventCreateWithFlags(&ev_fork, cudaEventDisableTiming);
        cudaEventCreateWithFlags(&ev_join, cudaEventDisableTiming);
    }

    const int TB = 256;
    int gE4 = (NE / 4 + TB - 1) / TB;
    int gW = (NN * 32 + TB - 1) / TB;
    int gC = (NCHUNK + 7) / 8;

    // fork: GEMM (independent of edge preprocessing) runs on s2
    cudaEventRecord(ev_fork, 0);
    cudaStreamWaitEvent(s2, ev_fork, 0);
    k_gemm_tc<<<(NN + 127) / 128, 256, 0, s2>>>(x, t1w, t1b, attl, attr);
    cudaEventRecord(ev_join, s2);

    // edge preprocessing on main stream, concurrent with GEMM
    k_hist<<<gE4, TB>>>(dst);
    k_scan<<<1, 1024>>>();
    k_fill<<<gE4, TB>>>(src, dst);

    // join: layers need both CSR and GEMM outputs
    cudaStreamWaitEvent(0, ev_join, 0);

    k_aggc<<<gC, TB>>>(0, 1, 0);
    k_attn<<<gW, TB>>>(1, 1, attl + 1 * HID, attr + 1 * HID);
    k_aggc<<<gC, TB>>>(1, 2, 1);
    k_attn<<<gW, TB>>>(2, 0, attl + 2 * HID, attr + 2 * HID);
    k_aggc<<<gC, TB>>>(2, 3, 0);

    k_head_mma<<<(NN + 127) / 128, 256>>>(3, t2w, t2b, out, write_emb);
}